// round 1
// baseline (speedup 1.0000x reference)
#include <cuda_runtime.h>

// GAE: g[t] = delta[t] + (GAMMA*LAM*nnt[t]) * g[t+1], scanned backward over T.
//   nnt[t]   = 1 - done[t+1]            (t < T-1),  1 - done[T-1] at t = T-1
//   nv[t]    = values[t+1]              (t < T-1),  next_value[b] at t = T-1
//   delta[t] = rewards[t] + GAMMA*nv[t]*nnt[t] - values[t]
//   advantages = g; returns = g + values
//
// One block per batch row, 256 threads, 8 elements/thread, affine-composition
// parallel scan for the backward recurrence.

#define GAMMA_F 0.99f
#define LAM_F   0.95f

static __device__ __forceinline__ float gl() { return GAMMA_F * LAM_F; }

#define THREADS 256
#define CHUNK   8

__global__ __launch_bounds__(THREADS, 8)
void gae_scan_kernel(const float* __restrict__ rewards,
                     const float* __restrict__ values,
                     const float* __restrict__ next_value,
                     const int*   __restrict__ done,
                     float* __restrict__ adv,
                     float* __restrict__ ret,
                     int T)
{
    __shared__ float sA[THREADS];
    __shared__ float sB[THREADS];

    const int b   = blockIdx.x;
    const int tid = threadIdx.x;
    const long long base = (long long)b * T;
    const int t0 = tid * CHUNK;

    // ---- coalesced vector loads ----
    const float4 r0 = *(const float4*)(rewards + base + t0);
    const float4 r1 = *(const float4*)(rewards + base + t0 + 4);
    const float4 v0 = *(const float4*)(values  + base + t0);
    const float4 v1 = *(const float4*)(values  + base + t0 + 4);
    const int4   d0 = *(const int4*)  (done    + base + t0);
    const int4   d1 = *(const int4*)  (done    + base + t0 + 4);

    const bool last_chunk = (t0 + CHUNK == T);
    const float v_extra = last_chunk ? next_value[b] : values[base + t0 + CHUNK];
    const int   d_extra = last_chunk ? d1.w          : done[base + t0 + CHUNK];

    float rw[CHUNK] = {r0.x, r0.y, r0.z, r0.w, r1.x, r1.y, r1.z, r1.w};
    float va[CHUNK] = {v0.x, v0.y, v0.z, v0.w, v1.x, v1.y, v1.z, v1.w};
    int   dn[CHUNK] = {d0.y, d0.z, d0.w, d1.x, d1.y, d1.z, d1.w, d_extra}; // done[t+1]
    float nv[CHUNK] = {va[1], va[2], va[3], va[4], va[5], va[6], va[7], v_extra};

    float c[CHUNK], dl[CHUNK];
    #pragma unroll
    for (int k = 0; k < CHUNK; ++k) {
        float nnt = 1.0f - (float)dn[k];
        dl[k] = fmaf(GAMMA_F * nnt, nv[k], rw[k]) - va[k];
        c[k]  = gl() * nnt;
    }

    // ---- local affine op: g(t0) = A * g_in + Bv, where g_in = g at t0+CHUNK ----
    float A = 1.0f, Bv = 0.0f;
    #pragma unroll
    for (int k = CHUNK - 1; k >= 0; --k) {
        Bv = fmaf(c[k], Bv, dl[k]);
        A  = A * c[k];
    }

    // ---- block scan over 256 affine ops (suffix composition via reversed index) ----
    // j = reversed thread index; inclusive scan x_j = H_j o x_{j-1}
    const int j = (THREADS - 1) - tid;
    sA[j] = A; sB[j] = Bv;
    __syncthreads();

    #pragma unroll
    for (int d = 1; d < THREADS; d <<= 1) {
        float pa = 0.0f, pb = 0.0f;
        bool act = (j >= d);
        if (act) { pa = sA[j - d]; pb = sB[j - d]; }
        __syncthreads();
        if (act) {
            // cur o prev: (a2,b2) o (a1,b1) = (a2*a1, a2*b1 + b2)
            float a2 = sA[j], b2 = sB[j];
            sA[j] = a2 * pa;
            sB[j] = fmaf(a2, pb, b2);
        }
        __syncthreads();
    }

    // exclusive suffix applied to g(T)=0 -> just the b component
    const float g_in = (j >= 1) ? sB[j - 1] : 0.0f;

    // ---- replay chunk backward with resolved carry ----
    float g = g_in;
    float out[CHUNK];
    #pragma unroll
    for (int k = CHUNK - 1; k >= 0; --k) {
        g = fmaf(c[k], g, dl[k]);
        out[k] = g;
    }

    float4 a0 = make_float4(out[0], out[1], out[2], out[3]);
    float4 a1 = make_float4(out[4], out[5], out[6], out[7]);
    float4 q0 = make_float4(out[0] + va[0], out[1] + va[1], out[2] + va[2], out[3] + va[3]);
    float4 q1 = make_float4(out[4] + va[4], out[5] + va[5], out[6] + va[6], out[7] + va[7]);

    *(float4*)(adv + base + t0)     = a0;
    *(float4*)(adv + base + t0 + 4) = a1;
    *(float4*)(ret + base + t0)     = q0;
    *(float4*)(ret + base + t0 + 4) = q1;
}

// Generic fallback (one thread per row, sequential backward scan) — only used
// if T is not CHUNK*THREADS.
__global__ void gae_fallback_kernel(const float* __restrict__ rewards,
                                    const float* __restrict__ values,
                                    const float* __restrict__ next_value,
                                    const int*   __restrict__ done,
                                    float* __restrict__ adv,
                                    float* __restrict__ ret,
                                    int B, int T)
{
    int b = blockIdx.x * blockDim.x + threadIdx.x;
    if (b >= B) return;
    const long long base = (long long)b * T;
    float g = 0.0f;
    for (int t = T - 1; t >= 0; --t) {
        float dnext = (t == T - 1) ? (float)done[base + T - 1] : (float)done[base + t + 1];
        float nvv   = (t == T - 1) ? next_value[b]             : values[base + t + 1];
        float nnt   = 1.0f - dnext;
        float v     = values[base + t];
        float delta = fmaf(GAMMA_F * nnt, nvv, rewards[base + t]) - v;
        g = fmaf(gl() * nnt, g, delta);
        adv[base + t] = g;
        ret[base + t] = g + v;
    }
}

extern "C" void kernel_launch(void* const* d_in, const int* in_sizes, int n_in,
                              void* d_out, int out_size)
{
    const float* rewards    = (const float*)d_in[0];
    const float* values     = (const float*)d_in[1];
    const float* next_value = (const float*)d_in[2];
    const int*   done       = (const int*)d_in[3];

    const int B  = in_sizes[2];
    const int T  = in_sizes[0] / B;
    const long long BT = (long long)B * T;

    float* adv = (float*)d_out;
    float* ret = adv + BT;

    if (T == THREADS * CHUNK) {
        gae_scan_kernel<<<B, THREADS>>>(rewards, values, next_value, done, adv, ret, T);
    } else {
        int blk = 256;
        gae_fallback_kernel<<<(B + blk - 1) / blk, blk>>>(rewards, values, next_value,
                                                          done, adv, ret, B, T);
    }
}

// round 2
// speedup vs baseline: 1.0147x; 1.0147x over previous
#include <cuda_runtime.h>

// GAE backward linear recurrence, one block per batch row (B=4096, T=2048).
// g[t] = delta[t] + c[t]*g[t+1],  c[t] = GAMMA*LAM*(1-done[t+1])
// delta[t] = rewards[t] + GAMMA*nv[t]*(1-done[t+1]) - values[t]
// adv = g, ret = g + values.
//
// 256 threads x 8 elems. Per-thread affine op (A,B); warp shuffle scan (5 steps),
// one smem exchange for the 8 warp composites, serial cross-warp fold.

#define GAMMA_F 0.99f
#define LAM_F   0.95f
#define GL_F    (GAMMA_F * LAM_F)

#define THREADS 256
#define CHUNK   8
#define FULL    0xffffffffu

__global__ __launch_bounds__(THREADS, 8)
void gae_scan_kernel(const float* __restrict__ rewards,
                     const float* __restrict__ values,
                     const float* __restrict__ next_value,
                     const int*   __restrict__ done,
                     float* __restrict__ adv,
                     float* __restrict__ ret,
                     int T)
{
    __shared__ float sWA[THREADS / 32];
    __shared__ float sWB[THREADS / 32];

    const int b    = blockIdx.x;
    const int tid  = threadIdx.x;
    const int lane = tid & 31;
    const int w    = tid >> 5;
    const long long base = (long long)b * T;
    const int t0 = tid * CHUNK;

    // ---- coalesced streaming vector loads ----
    const float4 r0 = __ldcs((const float4*)(rewards + base + t0));
    const float4 r1 = __ldcs((const float4*)(rewards + base + t0 + 4));
    const float4 v0 = __ldcs((const float4*)(values  + base + t0));
    const float4 v1 = __ldcs((const float4*)(values  + base + t0 + 4));
    const int4   d0 = __ldcs((const int4*)  (done    + base + t0));
    const int4   d1 = __ldcs((const int4*)  (done    + base + t0 + 4));

    // ---- neighbor handoff: thread tid needs values[t0+8], done[t0+8]
    //      which are lane+1's (v0.x, d0.x). Only lane 31 loads from global.
    float v_next = __shfl_down_sync(FULL, v0.x, 1);
    int   d_next = __shfl_down_sync(FULL, d0.x, 1);
    if (lane == 31) {
        if (tid == THREADS - 1) {           // last chunk of the row
            v_next = next_value[b];
            d_next = d1.w;                  // done[T-1] per reference edge rule
        } else {
            v_next = values[base + t0 + CHUNK];
            d_next = done[base + t0 + CHUNK];
        }
    }

    float rw[CHUNK] = {r0.x, r0.y, r0.z, r0.w, r1.x, r1.y, r1.z, r1.w};
    float va[CHUNK] = {v0.x, v0.y, v0.z, v0.w, v1.x, v1.y, v1.z, v1.w};
    int   dn[CHUNK] = {d0.y, d0.z, d0.w, d1.x, d1.y, d1.z, d1.w, d_next}; // done[t+1]
    float nv[CHUNK] = {va[1], va[2], va[3], va[4], va[5], va[6], va[7], v_next};

    float c[CHUNK], dl[CHUNK];
    #pragma unroll
    for (int k = 0; k < CHUNK; ++k) {
        float nnt = 1.0f - (float)dn[k];
        dl[k] = fmaf(GAMMA_F * nnt, nv[k], rw[k]) - va[k];
        c[k]  = GL_F * nnt;
    }

    // ---- local affine op: g(t0) = A * g(t0+CHUNK) + Bv ----
    float A = 1.0f, Bv = 0.0f;
    #pragma unroll
    for (int k = CHUNK - 1; k >= 0; --k) {
        Bv = fmaf(c[k], Bv, dl[k]);
        A  = A * c[k];
    }

    // ---- warp-segmented inclusive scan over DESCENDING tid (shfl_down) ----
    // IncA/IncB at lane = composition of ops for lanes [lane..31] of this warp
    // (highest lane = closest to T applied first).
    float IncA = A, IncB = Bv;
    #pragma unroll
    for (int d = 1; d < 32; d <<= 1) {
        float pa = __shfl_down_sync(FULL, IncA, d);
        float pb = __shfl_down_sync(FULL, IncB, d);
        if (lane + d < 32) {
            IncB = fmaf(IncA, pb, IncB);   // (cur ∘ prev): prev applied first
            IncA = IncA * pa;
        }
    }

    // lane 0 holds the whole-warp composite
    if (lane == 0) { sWA[w] = IncA; sWB[w] = IncB; }
    __syncthreads();

    // ---- cross-warp suffix composite S_w = W_{w+1} ∘ ... ∘ W_7 (W_7 first) ----
    float Sa = 1.0f, Sb = 0.0f;
    #pragma unroll
    for (int ww = (THREADS / 32) - 1; ww >= 1; --ww) {
        if (ww > w) {
            float wa = sWA[ww], wb = sWB[ww];
            Sb = fmaf(wa, Sb, wb);         // S <- W_ww ∘ S
            Sa = wa * Sa;
        }
    }

    // ---- exclusive within-warp (lanes lane+1..31), then apply to S(0)=Sb ----
    float ExcA = __shfl_down_sync(FULL, IncA, 1);
    float ExcB = __shfl_down_sync(FULL, IncB, 1);
    if (lane == 31) { ExcA = 1.0f; ExcB = 0.0f; }
    const float g_in = fmaf(ExcA, Sb, ExcB);   // g at t0+CHUNK

    // ---- replay chunk backward with resolved carry ----
    float g = g_in;
    float out[CHUNK];
    #pragma unroll
    for (int k = CHUNK - 1; k >= 0; --k) {
        g = fmaf(c[k], g, dl[k]);
        out[k] = g;
    }

    const float4 a0 = make_float4(out[0], out[1], out[2], out[3]);
    const float4 a1 = make_float4(out[4], out[5], out[6], out[7]);
    const float4 q0 = make_float4(out[0] + va[0], out[1] + va[1],
                                  out[2] + va[2], out[3] + va[3]);
    const float4 q1 = make_float4(out[4] + va[4], out[5] + va[5],
                                  out[6] + va[6], out[7] + va[7]);

    __stcs((float4*)(adv + base + t0),     a0);
    __stcs((float4*)(adv + base + t0 + 4), a1);
    __stcs((float4*)(ret + base + t0),     q0);
    __stcs((float4*)(ret + base + t0 + 4), q1);
}

// Generic fallback (one thread per row, sequential backward scan) — only used
// if T != CHUNK*THREADS.
__global__ void gae_fallback_kernel(const float* __restrict__ rewards,
                                    const float* __restrict__ values,
                                    const float* __restrict__ next_value,
                                    const int*   __restrict__ done,
                                    float* __restrict__ adv,
                                    float* __restrict__ ret,
                                    int B, int T)
{
    int b = blockIdx.x * blockDim.x + threadIdx.x;
    if (b >= B) return;
    const long long base = (long long)b * T;
    float g = 0.0f;
    for (int t = T - 1; t >= 0; --t) {
        float dnext = (t == T - 1) ? (float)done[base + T - 1] : (float)done[base + t + 1];
        float nvv   = (t == T - 1) ? next_value[b]             : values[base + t + 1];
        float nnt   = 1.0f - dnext;
        float v     = values[base + t];
        float delta = fmaf(GAMMA_F * nnt, nvv, rewards[base + t]) - v;
        g = fmaf(GL_F * nnt, g, delta);
        adv[base + t] = g;
        ret[base + t] = g + v;
    }
}

extern "C" void kernel_launch(void* const* d_in, const int* in_sizes, int n_in,
                              void* d_out, int out_size)
{
    const float* rewards    = (const float*)d_in[0];
    const float* values     = (const float*)d_in[1];
    const float* next_value = (const float*)d_in[2];
    const int*   done       = (const int*)d_in[3];

    const int B  = in_sizes[2];
    const int T  = in_sizes[0] / B;
    const long long BT = (long long)B * T;

    float* adv = (float*)d_out;
    float* ret = adv + BT;

    if (T == THREADS * CHUNK) {
        gae_scan_kernel<<<B, THREADS>>>(rewards, values, next_value, done, adv, ret, T);
    } else {
        int blk = 256;
        gae_fallback_kernel<<<(B + blk - 1) / blk, blk>>>(rewards, values, next_value,
                                                          done, adv, ret, B, T);
    }
}